// round 1
// baseline (speedup 1.0000x reference)
#include <cuda_runtime.h>
#include <cuda_bf16.h>
#include <math.h>

// Problem constants (HGCF_3221225472207)
constexpr int NN = 50000;   // nodes
constexpr int CC = 64;      // classes
constexpr int GG = 3;       // metapath graphs
constexpr int EE = 1200000; // edges per graph
constexpr int DD = 256;     // input feat dim
constexpr int HH = 256;     // hidden dim

// ---------------- device scratch (static, no allocation) ----------------
__device__ int   d_rowptr[GG * (NN + 1)];
__device__ int   d_cursor[GG * NN];      // deg, then cursor
__device__ int   d_srcs[GG * EE];        // src sorted by dst
__device__ float d_ea0[GG * EE];         // exp(e) layer 0, sorted by dst
__device__ float d_ea1[GG * EE];         // exp(e) layer 1, sorted by dst
__device__ float d_h[(size_t)NN * CC];   // propagation ping buffer
__device__ float d_hm[(size_t)NN * HH];  // MLP hidden
__device__ float d_lp_fb[(size_t)NN * CC]; // fallback if out_size small
__device__ float d_ns_fb[(size_t)NN * CC];

// ---------------- CSR build ----------------
__global__ void zero_deg_kernel() {
    int i = blockIdx.x * blockDim.x + threadIdx.x;
    if (i < GG * NN) d_cursor[i] = 0;
}

__global__ void hist_kernel(const int* __restrict__ dst) {
    int i = blockIdx.x * blockDim.x + threadIdx.x;
    if (i >= GG * EE) return;
    int g = i / EE;
    atomicAdd(&d_cursor[g * NN + dst[i]], 1);
}

__global__ void scan_kernel() {
    int g = blockIdx.x;
    int tid = threadIdx.x;
    __shared__ int sh[1024];
    __shared__ int sOff;
    if (tid == 0) sOff = 0;
    __syncthreads();
    for (int base = 0; base < NN; base += 1024) {
        int i = base + tid;
        int v = (i < NN) ? d_cursor[g * NN + i] : 0;
        sh[tid] = v;
        __syncthreads();
        #pragma unroll
        for (int dlt = 1; dlt < 1024; dlt <<= 1) {
            int t = (tid >= dlt) ? sh[tid - dlt] : 0;
            __syncthreads();
            sh[tid] += t;
            __syncthreads();
        }
        int excl = sOff + sh[tid] - v;
        if (i < NN) {
            d_rowptr[g * (NN + 1) + i] = excl;
            d_cursor[g * NN + i] = excl;  // cursor = start offset
        }
        int total = sh[1023];
        __syncthreads();
        if (tid == 0) sOff += total;
        __syncthreads();
    }
    if (tid == 0) d_rowptr[g * (NN + 1) + NN] = sOff;
}

__global__ void scatter_kernel(const int* __restrict__ src,
                               const int* __restrict__ dst,
                               const float* __restrict__ e_edges) {
    int i = blockIdx.x * blockDim.x + threadIdx.x;
    if (i >= GG * EE) return;
    int g = i / EE;
    int v = dst[i];
    int p = atomicAdd(&d_cursor[g * NN + v], 1);
    int idx = g * EE + p;
    d_srcs[idx] = src[i];
    // e_edges layout [L, G, E]: layer0 at i, layer1 at GG*EE + i
    d_ea0[idx] = expf(e_edges[i]);
    d_ea1[idx] = expf(e_edges[(size_t)GG * EE + i]);
}

// ---------------- propagation: one warp per dst node ----------------
// mode 0: write clamped h to h_out
// mode 1: accumulate att_softmax[:,gidx] * clamped h into lp_out
__global__ void propagate_kernel(const float* __restrict__ h_in,
                                 const float* __restrict__ ea,
                                 const int*   __restrict__ rowptr,
                                 const int*   __restrict__ srcs,
                                 const float* __restrict__ train_mask,
                                 const float* __restrict__ labels_oh,
                                 const float* __restrict__ attention,
                                 int gidx, int mode,
                                 float* __restrict__ h_out,
                                 float* __restrict__ lp_out) {
    int warp = (blockIdx.x * blockDim.x + threadIdx.x) >> 5;
    int lane = threadIdx.x & 31;
    if (warp >= NN) return;
    int beg = rowptr[warp];
    int end = rowptr[warp + 1];

    // denominator: sum of exp(e) over incoming edges
    float s = 0.f;
    for (int j = beg + lane; j < end; j += 32) s += ea[j];
    #pragma unroll
    for (int o = 16; o; o >>= 1) s += __shfl_xor_sync(0xffffffffu, s, o);
    float inv = (end > beg) ? 1.f / s : 0.f;

    float acc0 = 0.f, acc1 = 0.f;
    for (int j = beg; j < end; j++) {
        float w = ea[j] * inv;
        int sv = srcs[j];
        const float* hp = h_in + (size_t)sv * CC;
        acc0 = fmaf(hp[lane],      w, acc0);
        acc1 = fmaf(hp[lane + 32], w, acc1);
    }

    float tm = train_mask[warp];
    float ml = 1.f - tm;
    size_t i0 = (size_t)warp * CC + lane;
    float o0 = acc0 * ml + labels_oh[i0]      * tm;
    float o1 = acc1 * ml + labels_oh[i0 + 32] * tm;

    if (mode == 0) {
        h_out[i0]      = o0;
        h_out[i0 + 32] = o1;
    } else {
        float a0 = attention[warp * 3 + 0];
        float a1 = attention[warp * 3 + 1];
        float a2 = attention[warp * 3 + 2];
        float mx = fmaxf(a0, fmaxf(a1, a2));
        float e0 = expf(a0 - mx), e1 = expf(a1 - mx), e2 = expf(a2 - mx);
        float den = e0 + e1 + e2;
        float att = ((gidx == 0) ? e0 : (gidx == 1) ? e1 : e2) / den;
        if (gidx == 0) {
            lp_out[i0]      = att * o0;
            lp_out[i0 + 32] = att * o1;
        } else {
            lp_out[i0]      += att * o0;
            lp_out[i0 + 32] += att * o1;
        }
    }
}

// ---------------- SGEMM: C[M,Nc] = A[M,K] @ B[K,Nc] + bias (opt relu) ----
// BM=128, BN=64, BK=16, 256 threads, 8x4 per-thread microtile
template <bool RELU>
__global__ void sgemm_kernel(int M, int K, int Nc,
                             const float* __restrict__ A,
                             const float* __restrict__ B,
                             const float* __restrict__ bias,
                             float* __restrict__ C) {
    __shared__ float As[16][128 + 4];
    __shared__ float Bs[16][64];
    int tid = threadIdx.x;
    int tx = tid & 15;        // 0..15 -> cols
    int ty = tid >> 4;        // 0..15 -> rows
    int bm = blockIdx.y * 128;
    int bn = blockIdx.x * 64;

    float acc[8][4];
    #pragma unroll
    for (int i = 0; i < 8; i++)
        #pragma unroll
        for (int j = 0; j < 4; j++) acc[i][j] = 0.f;

    for (int k0 = 0; k0 < K; k0 += 16) {
        #pragma unroll
        for (int r = 0; r < 8; r++) {
            int lin = tid + r * 256;
            int m = lin >> 4, kk = lin & 15;
            int gm = bm + m;
            As[kk][m] = (gm < M) ? A[(size_t)gm * K + k0 + kk] : 0.f;
        }
        #pragma unroll
        for (int r = 0; r < 4; r++) {
            int lin = tid + r * 256;
            int kk = lin >> 6, n = lin & 63;
            Bs[kk][n] = B[(size_t)(k0 + kk) * Nc + bn + n];
        }
        __syncthreads();
        #pragma unroll
        for (int kk = 0; kk < 16; kk++) {
            float ra[8], rb[4];
            #pragma unroll
            for (int i = 0; i < 8; i++) ra[i] = As[kk][ty * 8 + i];
            #pragma unroll
            for (int j = 0; j < 4; j++) rb[j] = Bs[kk][tx * 4 + j];
            #pragma unroll
            for (int i = 0; i < 8; i++)
                #pragma unroll
                for (int j = 0; j < 4; j++)
                    acc[i][j] = fmaf(ra[i], rb[j], acc[i][j]);
        }
        __syncthreads();
    }

    #pragma unroll
    for (int i = 0; i < 8; i++) {
        int gm = bm + ty * 8 + i;
        if (gm >= M) continue;
        #pragma unroll
        for (int j = 0; j < 4; j++) {
            int gn = bn + tx * 4 + j;
            float v = acc[i][j] + bias[gn];
            if (RELU) v = fmaxf(v, 0.f);
            C[(size_t)gm * Nc + gn] = v;
        }
    }
}

// ---------------- final mix ----------------
__global__ void combine_kernel(const float* __restrict__ alpha,
                               const float* __restrict__ lp,
                               const float* __restrict__ ns,
                               float* __restrict__ out) {
    int i = blockIdx.x * blockDim.x + threadIdx.x;
    if (i >= NN * CC) return;
    int v = i >> 6;
    float a = alpha[v];
    float sg = 1.f / (1.f + expf(-a));
    out[i] = sg * lp[i] + (1.f - sg) * ns[i];
}

// ---------------- launch ----------------
extern "C" void kernel_launch(void* const* d_in, const int* in_sizes, int n_in,
                              void* d_out, int out_size) {
    const float* features0  = (const float*)d_in[0];
    const float* label_init = (const float*)d_in[1];
    const float* labels_oh  = (const float*)d_in[2];
    const float* train_mask = (const float*)d_in[3];
    const int*   src        = (const int*)d_in[4];
    const int*   dst        = (const int*)d_in[5];
    const float* e_edges    = (const float*)d_in[6];
    const float* attention  = (const float*)d_in[7];
    const float* alpha      = (const float*)d_in[8];
    const float* W1         = (const float*)d_in[9];
    const float* b1         = (const float*)d_in[10];
    const float* W2         = (const float*)d_in[11];
    const float* b2         = (const float*)d_in[12];

    float* out = (float*)d_out;
    float* lp;
    float* ns;
    if (out_size >= 3 * NN * CC) {
        lp = out + (size_t)NN * CC;
        ns = out + 2 * (size_t)NN * CC;
    } else {
        void* p;
        cudaGetSymbolAddress(&p, d_lp_fb); lp = (float*)p;
        cudaGetSymbolAddress(&p, d_ns_fb); ns = (float*)p;
    }

    // CSR build (per-graph sort by dst, exp(e) pre-applied for both layers)
    zero_deg_kernel<<<(GG * NN + 255) / 256, 256>>>();
    hist_kernel<<<(GG * EE + 255) / 256, 256>>>(dst);
    scan_kernel<<<GG, 1024>>>();
    scatter_kernel<<<(GG * EE + 255) / 256, 256>>>(src, dst, e_edges);

    // Label propagation: 3 graphs x 2 layers, one warp per node
    int pblocks = (NN * 32 + 255) / 256;
    float* hbuf;
    { void* p; cudaGetSymbolAddress(&p, d_h); hbuf = (float*)p; }
    float* hm;
    { void* p; cudaGetSymbolAddress(&p, d_hm); hm = (float*)p; }
    int* rowptr_base; { void* p; cudaGetSymbolAddress(&p, d_rowptr); rowptr_base = (int*)p; }
    int* srcs_base;   { void* p; cudaGetSymbolAddress(&p, d_srcs);   srcs_base   = (int*)p; }
    float* ea0_base;  { void* p; cudaGetSymbolAddress(&p, d_ea0);    ea0_base    = (float*)p; }
    float* ea1_base;  { void* p; cudaGetSymbolAddress(&p, d_ea1);    ea1_base    = (float*)p; }

    for (int g = 0; g < GG; g++) {
        propagate_kernel<<<pblocks, 256>>>(
            label_init, ea0_base + (size_t)g * EE,
            rowptr_base + g * (NN + 1), srcs_base + (size_t)g * EE,
            train_mask, labels_oh, attention, g, /*mode=*/0, hbuf, lp);
        propagate_kernel<<<pblocks, 256>>>(
            hbuf, ea1_base + (size_t)g * EE,
            rowptr_base + g * (NN + 1), srcs_base + (size_t)g * EE,
            train_mask, labels_oh, attention, g, /*mode=*/1, hbuf, lp);
    }

    // MLP: relu(F @ W1 + b1) @ W2 + b2
    {
        dim3 grid1(HH / 64, (NN + 127) / 128);
        sgemm_kernel<true><<<grid1, 256>>>(NN, DD, HH, features0, W1, b1, hm);
        dim3 grid2(CC / 64, (NN + 127) / 128);
        sgemm_kernel<false><<<grid2, 256>>>(NN, HH, CC, hm, W2, b2, ns);
    }

    // logits = sigmoid(alpha)*lp + sigmoid(-alpha)*ns
    combine_kernel<<<(NN * CC + 255) / 256, 256>>>(alpha, lp, ns, out);
}

// round 2
// speedup vs baseline: 1.1325x; 1.1325x over previous
#include <cuda_runtime.h>
#include <cuda_bf16.h>
#include <math.h>

// Problem constants (HGCF_3221225472207)
constexpr int NN = 50000;   // nodes
constexpr int CC = 64;      // classes
constexpr int GG = 3;       // metapath graphs
constexpr int EE = 1200000; // edges per graph
constexpr int DD = 256;     // input feat dim
constexpr int HH = 256;     // hidden dim
constexpr int NBLK = 49;    // ceil(NN/1024) scan blocks per graph

// ---------------- device scratch (static, no allocation) ----------------
__device__ int   d_rowptr[GG * (NN + 1)];
__device__ int   d_cursor[GG * NN];        // deg -> local-scan -> cursor
__device__ int   d_bsum[GG * 64];          // per-block sums for scan
__device__ int4  d_edges[(size_t)GG * EE]; // {src, exp(e_l0), exp(e_l1), 0} sorted by dst
__device__ float d_h[(size_t)NN * CC];     // propagation ping buffer
__device__ float d_hm[(size_t)NN * HH];    // MLP hidden
__device__ float d_lp_fb[(size_t)NN * CC]; // fallback if out_size small
__device__ float d_ns_fb[(size_t)NN * CC];

// ---------------- CSR build ----------------
__global__ void zero_deg_kernel() {
    int i = blockIdx.x * blockDim.x + threadIdx.x;
    if (i < GG * NN) d_cursor[i] = 0;
}

__global__ void hist_kernel(const int* __restrict__ dst) {
    int i = blockIdx.x * blockDim.x + threadIdx.x;
    if (i >= GG * EE) return;
    int g = i / EE;
    atomicAdd(&d_cursor[g * NN + dst[i]], 1);
}

// phase 1: per-1024-chunk exclusive scan (local), block totals to d_bsum
__global__ void scan1_kernel() {
    int g = blockIdx.y;
    int tid = threadIdx.x;
    int i = blockIdx.x * 1024 + tid;
    int v = (i < NN) ? d_cursor[g * NN + i] : 0;

    unsigned lane = tid & 31, w = tid >> 5;
    int x = v;
    #pragma unroll
    for (int o = 1; o < 32; o <<= 1) {
        int t = __shfl_up_sync(0xffffffffu, x, o);
        if (lane >= o) x += t;
    }
    __shared__ int wsum[32];
    if (lane == 31) wsum[w] = x;
    __syncthreads();
    if (w == 0) {
        int y = wsum[lane];
        #pragma unroll
        for (int o = 1; o < 32; o <<= 1) {
            int t = __shfl_up_sync(0xffffffffu, y, o);
            if (lane >= o) y += t;
        }
        wsum[lane] = y;
    }
    __syncthreads();
    int incl = x + (w > 0 ? wsum[w - 1] : 0);
    int excl = incl - v;
    if (i < NN) d_rowptr[g * (NN + 1) + i] = excl;  // local exclusive
    if (tid == 1023) d_bsum[g * 64 + blockIdx.x] = incl;  // block total
}

// phase 2: scan the block totals (tiny, serial per graph)
__global__ void scan2_kernel() {
    int g = threadIdx.x;
    if (g >= GG) return;
    int off = 0;
    for (int b = 0; b < NBLK; b++) {
        int t = d_bsum[g * 64 + b];
        d_bsum[g * 64 + b] = off;
        off += t;
    }
    d_rowptr[g * (NN + 1) + NN] = off;
}

// phase 3: add block offsets, init cursor
__global__ void scan3_kernel() {
    int i = blockIdx.x * blockDim.x + threadIdx.x;
    if (i >= GG * NN) return;
    int g = i / NN, n = i - g * NN;
    int val = d_rowptr[g * (NN + 1) + n] + d_bsum[g * 64 + (n >> 10)];
    d_rowptr[g * (NN + 1) + n] = val;
    d_cursor[g * NN + n] = val;
}

__global__ void scatter_kernel(const int* __restrict__ src,
                               const int* __restrict__ dst,
                               const float* __restrict__ e_edges) {
    int i = blockIdx.x * blockDim.x + threadIdx.x;
    if (i >= GG * EE) return;
    int g = i / EE;
    int v = dst[i];
    int p = atomicAdd(&d_cursor[g * NN + v], 1);
    float e0 = expf(e_edges[i]);                      // layer 0: [0, G*E) at i
    float e1 = expf(e_edges[(size_t)GG * EE + i]);    // layer 1
    d_edges[(size_t)g * EE + p] =
        make_int4(src[i], __float_as_int(e0), __float_as_int(e1), 0);
}

// ---------------- propagation: one warp per dst node ----------------
__global__ void propagate_kernel(const float* __restrict__ h_in,
                                 const int4*  __restrict__ edges,
                                 const int*   __restrict__ rowptr,
                                 const float* __restrict__ train_mask,
                                 const float* __restrict__ labels_oh,
                                 const float* __restrict__ attention,
                                 int gidx, int layer, int mode,
                                 float* __restrict__ h_out,
                                 float* __restrict__ lp_out) {
    int warp = (blockIdx.x * blockDim.x + threadIdx.x) >> 5;
    int lane = threadIdx.x & 31;
    if (warp >= NN) return;
    int beg = rowptr[warp];
    int end = rowptr[warp + 1];

    // denominator: sum of exp(e) over incoming edges
    float s = 0.f;
    for (int j = beg + lane; j < end; j += 32) {
        int4 e = edges[j];
        s += __int_as_float(layer ? e.z : e.y);
    }
    #pragma unroll
    for (int o = 16; o; o >>= 1) s += __shfl_xor_sync(0xffffffffu, s, o);
    float inv = (end > beg) ? 1.f / s : 0.f;

    float2 acc = make_float2(0.f, 0.f);
    #pragma unroll 4
    for (int j = beg; j < end; j++) {
        int4 e = edges[j];
        float w = __int_as_float(layer ? e.z : e.y) * inv;
        const float2* hp = (const float2*)(h_in + (size_t)e.x * CC);
        float2 v = hp[lane];
        acc.x = fmaf(v.x, w, acc.x);
        acc.y = fmaf(v.y, w, acc.y);
    }

    float tm = train_mask[warp];
    float ml = 1.f - tm;
    size_t i0 = (size_t)warp * CC + 2 * lane;
    float2 oh = *(const float2*)(labels_oh + i0);
    float2 o;
    o.x = acc.x * ml + oh.x * tm;
    o.y = acc.y * ml + oh.y * tm;

    if (mode == 0) {
        *(float2*)(h_out + i0) = o;
    } else {
        float a0 = attention[warp * 3 + 0];
        float a1 = attention[warp * 3 + 1];
        float a2 = attention[warp * 3 + 2];
        float mx = fmaxf(a0, fmaxf(a1, a2));
        float e0 = expf(a0 - mx), e1 = expf(a1 - mx), e2 = expf(a2 - mx);
        float den = e0 + e1 + e2;
        float att = ((gidx == 0) ? e0 : (gidx == 1) ? e1 : e2) / den;
        if (gidx == 0) {
            float2 r; r.x = att * o.x; r.y = att * o.y;
            *(float2*)(lp_out + i0) = r;
        } else {
            float2 cur = *(const float2*)(lp_out + i0);
            cur.x = fmaf(att, o.x, cur.x);
            cur.y = fmaf(att, o.y, cur.y);
            *(float2*)(lp_out + i0) = cur;
        }
    }
}

// ---------------- SGEMM: C[M,Nc] = A[M,K] @ B[K,Nc] + bias ----------------
// BM=128, BK=16, 256 threads, double-buffered, float4 everywhere.
// BN=128: 8x8 microtile (cols split tx*4 and 64+tx*4). BN=64: 8x4 microtile.
// COMBINE: also emit outFinal = sigmoid(alpha)*lp + sigmoid(-alpha)*C
template <int BN, int TN, bool RELU, bool COMBINE>
__global__ __launch_bounds__(256)
void sgemm_kernel(int M, int K, int Nc,
                  const float* __restrict__ A,
                  const float* __restrict__ B,
                  const float* __restrict__ bias,
                  float* __restrict__ C,
                  const float* __restrict__ alpha,
                  const float* __restrict__ lp,
                  float* __restrict__ outFinal) {
    constexpr int ASTRIDE = 132;
    constexpr int BSTRIDE = BN + 4;
    __shared__ float As[2][16][ASTRIDE];
    __shared__ float Bs[2][16][BSTRIDE];

    int tid = threadIdx.x;
    int tx = tid & 15;        // 16 col groups
    int ty = tid >> 4;        // 16 row groups
    int bm = blockIdx.y * 128;
    int bn = blockIdx.x * BN;

    // ---- A load mapping: thread loads float4 at (row = tid/4 [+64], kcol4 = tid%4)
    int a_row = tid >> 2;
    int a_c4  = tid & 3;
    // ---- B load mapping
    //   BN=128: 512 float4 per tile, 2 per thread: row = tid/32 [+8], col4 = tid%32
    //   BN=64 : 256 float4 per tile, 1 per thread: row = tid/16, col4 = tid%16
    int b_row = (BN == 128) ? (tid >> 5) : (tid >> 4);
    int b_c4  = (BN == 128) ? (tid & 31) : (tid & 15);

    float acc[8][TN];
    #pragma unroll
    for (int i = 0; i < 8; i++)
        #pragma unroll
        for (int j = 0; j < TN; j++) acc[i][j] = 0.f;

    int numTiles = K / 16;

    float4 a0, a1, b0, b1;
    auto ldg_tile = [&](int t) {
        int k0 = t * 16;
        int gm0 = bm + a_row;
        int gm1 = bm + a_row + 64;
        a0 = (gm0 < M) ? *(const float4*)(A + (size_t)gm0 * K + k0 + a_c4 * 4)
                       : make_float4(0.f, 0.f, 0.f, 0.f);
        a1 = (gm1 < M) ? *(const float4*)(A + (size_t)gm1 * K + k0 + a_c4 * 4)
                       : make_float4(0.f, 0.f, 0.f, 0.f);
        b0 = *(const float4*)(B + (size_t)(k0 + b_row) * Nc + bn + b_c4 * 4);
        if (BN == 128)
            b1 = *(const float4*)(B + (size_t)(k0 + b_row + 8) * Nc + bn + b_c4 * 4);
    };
    auto sts_tile = [&](int buf) {
        As[buf][a_c4 * 4 + 0][a_row] = a0.x;
        As[buf][a_c4 * 4 + 1][a_row] = a0.y;
        As[buf][a_c4 * 4 + 2][a_row] = a0.z;
        As[buf][a_c4 * 4 + 3][a_row] = a0.w;
        As[buf][a_c4 * 4 + 0][a_row + 64] = a1.x;
        As[buf][a_c4 * 4 + 1][a_row + 64] = a1.y;
        As[buf][a_c4 * 4 + 2][a_row + 64] = a1.z;
        As[buf][a_c4 * 4 + 3][a_row + 64] = a1.w;
        *(float4*)&Bs[buf][b_row][b_c4 * 4] = b0;
        if (BN == 128) *(float4*)&Bs[buf][b_row + 8][b_c4 * 4] = b1;
    };

    ldg_tile(0);
    sts_tile(0);
    __syncthreads();

    for (int t = 0; t < numTiles; t++) {
        int cur = t & 1;
        if (t + 1 < numTiles) ldg_tile(t + 1);
        #pragma unroll
        for (int kk = 0; kk < 16; kk++) {
            float4 ra0 = *(const float4*)&As[cur][kk][ty * 8];
            float4 ra1 = *(const float4*)&As[cur][kk][ty * 8 + 4];
            float4 rb0 = *(const float4*)&Bs[cur][kk][tx * 4];
            float ra[8] = {ra0.x, ra0.y, ra0.z, ra0.w, ra1.x, ra1.y, ra1.z, ra1.w};
            float rb[TN];
            rb[0] = rb0.x; rb[1] = rb0.y; rb[2] = rb0.z; rb[3] = rb0.w;
            if (TN == 8) {
                float4 rb1 = *(const float4*)&Bs[cur][kk][64 + tx * 4];
                rb[4] = rb1.x; rb[5] = rb1.y; rb[6] = rb1.z; rb[7] = rb1.w;
            }
            #pragma unroll
            for (int i = 0; i < 8; i++)
                #pragma unroll
                for (int j = 0; j < TN; j++)
                    acc[i][j] = fmaf(ra[i], rb[j], acc[i][j]);
        }
        if (t + 1 < numTiles) sts_tile((t + 1) & 1);
        __syncthreads();
    }

    // epilogue
    float4 bia0 = *(const float4*)(bias + bn + tx * 4);
    float4 bia1 = (TN == 8) ? *(const float4*)(bias + bn + 64 + tx * 4)
                            : make_float4(0.f, 0.f, 0.f, 0.f);
    #pragma unroll
    for (int i = 0; i < 8; i++) {
        int gm = bm + ty * 8 + i;
        if (gm >= M) continue;
        float4 v0;
        v0.x = acc[i][0] + bia0.x; v0.y = acc[i][1] + bia0.y;
        v0.z = acc[i][2] + bia0.z; v0.w = acc[i][3] + bia0.w;
        if (RELU) {
            v0.x = fmaxf(v0.x, 0.f); v0.y = fmaxf(v0.y, 0.f);
            v0.z = fmaxf(v0.z, 0.f); v0.w = fmaxf(v0.w, 0.f);
        }
        size_t idx0 = (size_t)gm * Nc + bn + tx * 4;
        *(float4*)(C + idx0) = v0;
        if (TN == 8) {
            float4 v1;
            v1.x = acc[i][4] + bia1.x; v1.y = acc[i][5] + bia1.y;
            v1.z = acc[i][6] + bia1.z; v1.w = acc[i][7] + bia1.w;
            if (RELU) {
                v1.x = fmaxf(v1.x, 0.f); v1.y = fmaxf(v1.y, 0.f);
                v1.z = fmaxf(v1.z, 0.f); v1.w = fmaxf(v1.w, 0.f);
            }
            *(float4*)(C + idx0 + 64) = v1;
        }
        if (COMBINE) {
            float a = alpha[gm];
            float sg = 1.f / (1.f + expf(-a));
            float4 l0 = *(const float4*)(lp + idx0);
            float4 r0;
            r0.x = sg * l0.x + (1.f - sg) * v0.x;
            r0.y = sg * l0.y + (1.f - sg) * v0.y;
            r0.z = sg * l0.z + (1.f - sg) * v0.z;
            r0.w = sg * l0.w + (1.f - sg) * v0.w;
            *(float4*)(outFinal + idx0) = r0;
        }
    }
}

// ---------------- launch ----------------
extern "C" void kernel_launch(void* const* d_in, const int* in_sizes, int n_in,
                              void* d_out, int out_size) {
    const float* features0  = (const float*)d_in[0];
    const float* label_init = (const float*)d_in[1];
    const float* labels_oh  = (const float*)d_in[2];
    const float* train_mask = (const float*)d_in[3];
    const int*   src        = (const int*)d_in[4];
    const int*   dst        = (const int*)d_in[5];
    const float* e_edges    = (const float*)d_in[6];
    const float* attention  = (const float*)d_in[7];
    const float* alpha      = (const float*)d_in[8];
    const float* W1         = (const float*)d_in[9];
    const float* b1         = (const float*)d_in[10];
    const float* W2         = (const float*)d_in[11];
    const float* b2         = (const float*)d_in[12];

    float* out = (float*)d_out;
    float* lp;
    float* ns;
    if (out_size >= 3 * NN * CC) {
        lp = out + (size_t)NN * CC;
        ns = out + 2 * (size_t)NN * CC;
    } else {
        void* p;
        cudaGetSymbolAddress(&p, d_lp_fb); lp = (float*)p;
        cudaGetSymbolAddress(&p, d_ns_fb); ns = (float*)p;
    }

    float* hbuf; { void* p; cudaGetSymbolAddress(&p, d_h);  hbuf = (float*)p; }
    float* hm;   { void* p; cudaGetSymbolAddress(&p, d_hm); hm   = (float*)p; }
    int* rowptr_base; { void* p; cudaGetSymbolAddress(&p, d_rowptr); rowptr_base = (int*)p; }
    int4* edges_base; { void* p; cudaGetSymbolAddress(&p, d_edges);  edges_base  = (int4*)p; }

    // CSR build: hist -> 3-phase parallel scan -> packed scatter
    zero_deg_kernel<<<(GG * NN + 255) / 256, 256>>>();
    hist_kernel<<<(GG * EE + 255) / 256, 256>>>(dst);
    { dim3 g1(NBLK, GG); scan1_kernel<<<g1, 1024>>>(); }
    scan2_kernel<<<1, 32>>>();
    scan3_kernel<<<(GG * NN + 255) / 256, 256>>>();
    scatter_kernel<<<(GG * EE + 255) / 256, 256>>>(src, dst, e_edges);

    // MLP GEMM1 first (independent of propagation; its weights are hot anyway)
    {
        dim3 grid1(HH / 128, (NN + 127) / 128);
        sgemm_kernel<128, 8, true, false><<<grid1, 256>>>(
            NN, DD, HH, features0, W1, b1, hm, nullptr, nullptr, nullptr);
    }

    // Label propagation: 3 graphs x 2 layers, one warp per node
    int pblocks = (NN * 32 + 255) / 256;
    for (int g = 0; g < GG; g++) {
        propagate_kernel<<<pblocks, 256>>>(
            label_init, edges_base + (size_t)g * EE,
            rowptr_base + g * (NN + 1),
            train_mask, labels_oh, attention, g, /*layer=*/0, /*mode=*/0, hbuf, lp);
        propagate_kernel<<<pblocks, 256>>>(
            hbuf, edges_base + (size_t)g * EE,
            rowptr_base + g * (NN + 1),
            train_mask, labels_oh, attention, g, /*layer=*/1, /*mode=*/1, hbuf, lp);
    }

    // GEMM2 with fused final combine: ns = hm@W2+b2; out = sig(a)*lp + sig(-a)*ns
    {
        dim3 grid2(CC / 64, (NN + 127) / 128);
        sgemm_kernel<64, 4, false, true><<<grid2, 256>>>(
            NN, HH, CC, hm, W2, b2, ns, alpha, lp, out);
    }
}

// round 4
// speedup vs baseline: 1.3923x; 1.2294x over previous
#include <cuda_runtime.h>
#include <cuda_bf16.h>
#include <math.h>
#include <cstdint>

// Problem constants (HGCF_3221225472207)
constexpr int NN = 50000;   // nodes
constexpr int CC = 64;      // classes
constexpr int GG = 3;       // metapath graphs
constexpr int EE = 1200000; // edges per graph
constexpr int DD = 256;     // input feat dim
constexpr int HH = 256;     // hidden dim
constexpr int NBLK = 49;    // ceil(NN/1024) scan blocks per graph
constexpr int MT = (NN + 127) / 128; // 391 M-tiles

// ---------------- device scratch (static, no allocation) ----------------
__device__ int   d_rowptr[GG * (NN + 1)];
__device__ int   d_cursor[GG * NN];
__device__ int   d_bsum[GG * 64];
__device__ int4  d_edges[(size_t)GG * EE];
__device__ float d_h[(size_t)NN * CC];
__device__ float d_lp_fb[(size_t)NN * CC];
__device__ float d_ns_fb[(size_t)NN * CC];
// bf16 split operands
__device__ __nv_bfloat16 d_Ahi[(size_t)NN * DD];
__device__ __nv_bfloat16 d_Alo[(size_t)NN * DD];
__device__ __nv_bfloat16 d_W1Thi[HH * DD];   // [n=256, k=256] = W1^T
__device__ __nv_bfloat16 d_W1Tlo[HH * DD];
__device__ __nv_bfloat16 d_HMhi[(size_t)NN * HH];
__device__ __nv_bfloat16 d_HMlo[(size_t)NN * HH];
__device__ __nv_bfloat16 d_W2Thi[CC * HH];   // [n=64, k=256] = W2^T
__device__ __nv_bfloat16 d_W2Tlo[CC * HH];

// ---------------- warp MMA helpers (compute_80+, works on compute_103) ----
__device__ __forceinline__ uint32_t smem_u32(const void* p) {
    uint32_t a;
    asm("{ .reg .u64 t; cvta.to.shared.u64 t, %1; cvt.u32.u64 %0, t; }" : "=r"(a) : "l"(p));
    return a;
}
__device__ __forceinline__ void ldsm_x4(uint32_t (&r)[4], uint32_t addr) {
    asm volatile("ldmatrix.sync.aligned.m8n8.x4.shared.b16 {%0,%1,%2,%3}, [%4];"
                 : "=r"(r[0]), "=r"(r[1]), "=r"(r[2]), "=r"(r[3]) : "r"(addr));
}
__device__ __forceinline__ void mma_bf16(float* c, const uint32_t (&a)[4],
                                         uint32_t b0, uint32_t b1) {
    asm volatile(
        "mma.sync.aligned.m16n8k16.row.col.f32.bf16.bf16.f32 "
        "{%0,%1,%2,%3}, {%4,%5,%6,%7}, {%8,%9}, {%0,%1,%2,%3};"
        : "+f"(c[0]), "+f"(c[1]), "+f"(c[2]), "+f"(c[3])
        : "r"(a[0]), "r"(a[1]), "r"(a[2]), "r"(a[3]), "r"(b0), "r"(b1));
}

// ---------------- bf16 split conversion kernels ----------------
__global__ void convA_kernel(const float* __restrict__ x,
                             __nv_bfloat16* __restrict__ hi,
                             __nv_bfloat16* __restrict__ lo, int n4) {
    int i = blockIdx.x * blockDim.x + threadIdx.x;
    if (i >= n4) return;
    float4 v = ((const float4*)x)[i];
    __nv_bfloat16 h[4], l[4];
    float vv[4] = {v.x, v.y, v.z, v.w};
    #pragma unroll
    for (int j = 0; j < 4; j++) {
        h[j] = __float2bfloat16(vv[j]);
        l[j] = __float2bfloat16(vv[j] - __bfloat162float(h[j]));
    }
    ((uint2*)hi)[i] = *(uint2*)h;
    ((uint2*)lo)[i] = *(uint2*)l;
}

// transpose + split: out[n*K + k] = in[k*Nc + n]
__global__ void convWT_kernel(const float* __restrict__ in,
                              __nv_bfloat16* __restrict__ hi,
                              __nv_bfloat16* __restrict__ lo, int K, int Nc) {
    int i = blockIdx.x * blockDim.x + threadIdx.x;
    if (i >= K * Nc) return;
    int n = i / K, k = i - n * K;
    float v = in[(size_t)k * Nc + n];
    __nv_bfloat16 h = __float2bfloat16(v);
    hi[i] = h;
    lo[i] = __float2bfloat16(v - __bfloat162float(h));
}

// ---------------- HMMA split GEMM ----------------
// C[M, Ntile] = Ahi*Bhi + Alo*Bhi + Ahi*Blo, K=256, fp32 accum.
// A: [M,256] bf16 row-major. B: [Ntot,256] bf16 (W^T, n-major rows of k).
// BM=128, BK=32, 256 threads (8 warps).
//   BN=128: warps 2x4, warp tile 64x32 (MF=4 m-frags, NP=2 n-frag-pairs)
//   BN=64 : warps 4x2, warp tile 32x32 (MF=2, NP=2)
// Smem rows padded to 40 bf16 (80B, 20 banks) -> conflict-free ldmatrix.
template <int BN, bool COMBINE>
__global__ void __launch_bounds__(256) hmma_gemm_kernel(
    const __nv_bfloat16* __restrict__ Ahi, const __nv_bfloat16* __restrict__ Alo,
    const __nv_bfloat16* __restrict__ Bhi, const __nv_bfloat16* __restrict__ Blo,
    int M, const float* __restrict__ bias,
    __nv_bfloat16* __restrict__ outHi, __nv_bfloat16* __restrict__ outLo,
    const float* __restrict__ alpha, const float* __restrict__ lp,
    float* __restrict__ ns, float* __restrict__ outF) {
    constexpr int STRIDE = 40;                   // bf16 units per smem row
    constexpr int WARPS_M = (BN == 128) ? 2 : 4;
    constexpr int WARPS_N = (BN == 128) ? 4 : 2;
    constexpr int WM = 128 / WARPS_M;            // 64 or 32
    constexpr int MF = WM / 16;                  // 4 or 2
    constexpr int NP = 2;                        // 32 n per warp = 2 ldsm.x4

    __shared__ __nv_bfloat16 As[2][128 * STRIDE]; // [hi/lo]
    __shared__ __nv_bfloat16 Bs[2][BN * STRIDE];

    int tid = threadIdx.x;
    int wid = tid >> 5, lane = tid & 31;
    int bm = blockIdx.x * 128;
    int bn = blockIdx.y * BN;
    int wm0 = (wid / WARPS_N) * WM;
    int wn0 = (wid % WARPS_N) * 32;

    float acc[MF][2 * NP][4];
    #pragma unroll
    for (int i = 0; i < MF; i++)
        #pragma unroll
        for (int j = 0; j < 2 * NP; j++)
            #pragma unroll
            for (int q = 0; q < 4; q++) acc[i][j][q] = 0.f;

    uint32_t sA = smem_u32(As);
    uint32_t sB = smem_u32(Bs);
    // ldmatrix lane address pieces: row-in-frag = lane%16, chunk(8 bf16) = lane/16
    int lrow = lane & 15, lch = lane >> 4;

    for (int kt = 0; kt < 8; kt++) {
        int k0 = kt * 32;
        // load A tiles (hi+lo): 128 rows x 32 bf16 = 512 16B-chunks each
        #pragma unroll
        for (int j = 0; j < 2; j++) {
            int idx = j * 256 + tid;
            int row = idx >> 2, ch = idx & 3;
            int gm = bm + row;
            uint4 vh = make_uint4(0, 0, 0, 0), vl = make_uint4(0, 0, 0, 0);
            if (gm < M) {
                vh = *(const uint4*)(Ahi + (size_t)gm * 256 + k0 + ch * 8);
                vl = *(const uint4*)(Alo + (size_t)gm * 256 + k0 + ch * 8);
            }
            *(uint4*)&As[0][row * STRIDE + ch * 8] = vh;
            *(uint4*)&As[1][row * STRIDE + ch * 8] = vl;
        }
        // load B tiles: BN rows x 32 bf16
        #pragma unroll
        for (int j = 0; j < BN / 64; j++) {
            int idx = j * 256 + tid;
            int row = idx >> 2, ch = idx & 3;
            uint4 vh = *(const uint4*)(Bhi + (size_t)(bn + row) * 256 + k0 + ch * 8);
            uint4 vl = *(const uint4*)(Blo + (size_t)(bn + row) * 256 + k0 + ch * 8);
            *(uint4*)&Bs[0][row * STRIDE + ch * 8] = vh;
            *(uint4*)&Bs[1][row * STRIDE + ch * 8] = vl;
        }
        __syncthreads();

        #pragma unroll
        for (int ks = 0; ks < 2; ks++) {
            uint32_t ah[MF][4], al[MF][4], bh[NP][4], bl[NP][4];
            #pragma unroll
            for (int mf = 0; mf < MF; mf++) {
                uint32_t off = ((wm0 + mf * 16 + lrow) * STRIDE + (ks * 2 + lch) * 8) * 2;
                ldsm_x4(ah[mf], sA + off);
                ldsm_x4(al[mf], sA + 128 * STRIDE * 2 + off);
            }
            #pragma unroll
            for (int np = 0; np < NP; np++) {
                uint32_t off = ((wn0 + np * 16 + lrow) * STRIDE + (ks * 2 + lch) * 8) * 2;
                ldsm_x4(bh[np], sB + off);
                ldsm_x4(bl[np], sB + BN * STRIDE * 2 + off);
            }
            #pragma unroll
            for (int mf = 0; mf < MF; mf++)
                #pragma unroll
                for (int np = 0; np < NP; np++) {
                    // n-frag even: regs {0,2}; odd: regs {1,3}
                    mma_bf16(acc[mf][2 * np + 0], ah[mf], bh[np][0], bh[np][2]);
                    mma_bf16(acc[mf][2 * np + 1], ah[mf], bh[np][1], bh[np][3]);
                    mma_bf16(acc[mf][2 * np + 0], al[mf], bh[np][0], bh[np][2]);
                    mma_bf16(acc[mf][2 * np + 1], al[mf], bh[np][1], bh[np][3]);
                    mma_bf16(acc[mf][2 * np + 0], ah[mf], bl[np][0], bl[np][2]);
                    mma_bf16(acc[mf][2 * np + 1], ah[mf], bl[np][1], bl[np][3]);
                }
        }
        __syncthreads();
    }

    // epilogue: c-frag thread t holds (m = t/4 [,+8], n = 2*(t%4)+{0,1})
    int mrow = lane >> 2, npair = lane & 3;
    #pragma unroll
    for (int mf = 0; mf < MF; mf++) {
        #pragma unroll
        for (int nf = 0; nf < 2 * NP; nf++) {
            int nloc = wn0 + nf * 8 + 2 * npair;
            int gn = bn + nloc;
            #pragma unroll
            for (int half = 0; half < 2; half++) {   // c01 (m) / c23 (m+8)
                int gm = bm + wm0 + mf * 16 + mrow + half * 8;
                if (gm >= M) continue;
                float v0 = acc[mf][nf][half * 2 + 0] + bias[gn];
                float v1 = acc[mf][nf][half * 2 + 1] + bias[gn + 1];
                if (!COMBINE) {
                    v0 = fmaxf(v0, 0.f);
                    v1 = fmaxf(v1, 0.f);
                    __nv_bfloat16 h0 = __float2bfloat16(v0);
                    __nv_bfloat16 h1 = __float2bfloat16(v1);
                    __nv_bfloat16 l0 = __float2bfloat16(v0 - __bfloat162float(h0));
                    __nv_bfloat16 l1 = __float2bfloat16(v1 - __bfloat162float(h1));
                    size_t base = (size_t)gm * 256 + gn;
                    __nv_bfloat162 hp; hp.x = h0; hp.y = h1;
                    __nv_bfloat162 lo2; lo2.x = l0; lo2.y = l1;
                    *(__nv_bfloat162*)(outHi + base) = hp;
                    *(__nv_bfloat162*)(outLo + base) = lo2;
                } else {
                    float sg = 1.f / (1.f + expf(-alpha[gm]));
                    size_t base = (size_t)gm * 64 + gn;
                    float2 l = *(const float2*)(lp + base);
                    float2 nsv; nsv.x = v0; nsv.y = v1;
                    float2 o;
                    o.x = sg * l.x + (1.f - sg) * v0;
                    o.y = sg * l.y + (1.f - sg) * v1;
                    *(float2*)(ns + base) = nsv;
                    *(float2*)(outF + base) = o;
                }
            }
        }
    }
}

// ---------------- CSR build ----------------
__global__ void zero_deg_kernel() {
    int i = blockIdx.x * blockDim.x + threadIdx.x;
    if (i < GG * NN) d_cursor[i] = 0;
}

__global__ void hist_kernel(const int* __restrict__ dst) {
    int i = blockIdx.x * blockDim.x + threadIdx.x;
    if (i >= GG * EE) return;
    int g = i / EE;
    atomicAdd(&d_cursor[g * NN + dst[i]], 1);
}

__global__ void scan1_kernel() {
    int g = blockIdx.y;
    int tid = threadIdx.x;
    int i = blockIdx.x * 1024 + tid;
    int v = (i < NN) ? d_cursor[g * NN + i] : 0;
    unsigned lane = tid & 31, w = tid >> 5;
    int x = v;
    #pragma unroll
    for (int o = 1; o < 32; o <<= 1) {
        int t = __shfl_up_sync(0xffffffffu, x, o);
        if (lane >= o) x += t;
    }
    __shared__ int wsum[32];
    if (lane == 31) wsum[w] = x;
    __syncthreads();
    if (w == 0) {
        int y = wsum[lane];
        #pragma unroll
        for (int o = 1; o < 32; o <<= 1) {
            int t = __shfl_up_sync(0xffffffffu, y, o);
            if (lane >= o) y += t;
        }
        wsum[lane] = y;
    }
    __syncthreads();
    int incl = x + (w > 0 ? wsum[w - 1] : 0);
    int excl = incl - v;
    if (i < NN) d_rowptr[g * (NN + 1) + i] = excl;
    if (tid == 1023) d_bsum[g * 64 + blockIdx.x] = incl;
}

__global__ void scan2_kernel() {
    int g = threadIdx.x;
    if (g >= GG) return;
    int off = 0;
    for (int b = 0; b < NBLK; b++) {
        int t = d_bsum[g * 64 + b];
        d_bsum[g * 64 + b] = off;
        off += t;
    }
    d_rowptr[g * (NN + 1) + NN] = off;
}

__global__ void scan3_kernel() {
    int i = blockIdx.x * blockDim.x + threadIdx.x;
    if (i >= GG * NN) return;
    int g = i / NN, n = i - g * NN;
    int val = d_rowptr[g * (NN + 1) + n] + d_bsum[g * 64 + (n >> 10)];
    d_rowptr[g * (NN + 1) + n] = val;
    d_cursor[g * NN + n] = val;
}

__global__ void scatter_kernel(const int* __restrict__ src,
                               const int* __restrict__ dst,
                               const float* __restrict__ e_edges) {
    int i = blockIdx.x * blockDim.x + threadIdx.x;
    if (i >= GG * EE) return;
    int g = i / EE;
    int v = dst[i];
    int p = atomicAdd(&d_cursor[g * NN + v], 1);
    float e0 = expf(e_edges[i]);
    float e1 = expf(e_edges[(size_t)GG * EE + i]);
    d_edges[(size_t)g * EE + p] =
        make_int4(src[i], __float_as_int(e0), __float_as_int(e1), 0);
}

// ---------------- propagation: one warp per dst node ----------------
__global__ void propagate_kernel(const float* __restrict__ h_in,
                                 const int4*  __restrict__ edges,
                                 const int*   __restrict__ rowptr,
                                 const float* __restrict__ train_mask,
                                 const float* __restrict__ labels_oh,
                                 const float* __restrict__ attention,
                                 int gidx, int layer, int mode,
                                 float* __restrict__ h_out,
                                 float* __restrict__ lp_out) {
    int warp = (blockIdx.x * blockDim.x + threadIdx.x) >> 5;
    int lane = threadIdx.x & 31;
    if (warp >= NN) return;
    int beg = rowptr[warp];
    int end = rowptr[warp + 1];

    float s = 0.f;
    for (int j = beg + lane; j < end; j += 32) {
        int4 e = edges[j];
        s += __int_as_float(layer ? e.z : e.y);
    }
    #pragma unroll
    for (int o = 16; o; o >>= 1) s += __shfl_xor_sync(0xffffffffu, s, o);
    float inv = (end > beg) ? 1.f / s : 0.f;

    float2 acc = make_float2(0.f, 0.f);
    #pragma unroll 4
    for (int j = beg; j < end; j++) {
        int4 e = edges[j];
        float w = __int_as_float(layer ? e.z : e.y) * inv;
        const float2* hp = (const float2*)(h_in + (size_t)e.x * CC);
        float2 v = hp[lane];
        acc.x = fmaf(v.x, w, acc.x);
        acc.y = fmaf(v.y, w, acc.y);
    }

    float tm = train_mask[warp];
    float ml = 1.f - tm;
    size_t i0 = (size_t)warp * CC + 2 * lane;
    float2 oh = *(const float2*)(labels_oh + i0);
    float2 o;
    o.x = acc.x * ml + oh.x * tm;
    o.y = acc.y * ml + oh.y * tm;

    if (mode == 0) {
        *(float2*)(h_out + i0) = o;
    } else {
        float a0 = attention[warp * 3 + 0];
        float a1 = attention[warp * 3 + 1];
        float a2 = attention[warp * 3 + 2];
        float mx = fmaxf(a0, fmaxf(a1, a2));
        float e0 = expf(a0 - mx), e1 = expf(a1 - mx), e2 = expf(a2 - mx);
        float den = e0 + e1 + e2;
        float att = ((gidx == 0) ? e0 : (gidx == 1) ? e1 : e2) / den;
        if (gidx == 0) {
            float2 r; r.x = att * o.x; r.y = att * o.y;
            *(float2*)(lp_out + i0) = r;
        } else {
            float2 cur = *(const float2*)(lp_out + i0);
            cur.x = fmaf(att, o.x, cur.x);
            cur.y = fmaf(att, o.y, cur.y);
            *(float2*)(lp_out + i0) = cur;
        }
    }
}

// ---------------- launch ----------------
extern "C" void kernel_launch(void* const* d_in, const int* in_sizes, int n_in,
                              void* d_out, int out_size) {
    const float* features0  = (const float*)d_in[0];
    const float* label_init = (const float*)d_in[1];
    const float* labels_oh  = (const float*)d_in[2];
    const float* train_mask = (const float*)d_in[3];
    const int*   src        = (const int*)d_in[4];
    const int*   dst        = (const int*)d_in[5];
    const float* e_edges    = (const float*)d_in[6];
    const float* attention  = (const float*)d_in[7];
    const float* alpha      = (const float*)d_in[8];
    const float* W1         = (const float*)d_in[9];
    const float* b1         = (const float*)d_in[10];
    const float* W2         = (const float*)d_in[11];
    const float* b2         = (const float*)d_in[12];

    float* out = (float*)d_out;
    float* lp;
    float* ns;
    if (out_size >= 3 * NN * CC) {
        lp = out + (size_t)NN * CC;
        ns = out + 2 * (size_t)NN * CC;
    } else {
        void* p;
        cudaGetSymbolAddress(&p, d_lp_fb); lp = (float*)p;
        cudaGetSymbolAddress(&p, d_ns_fb); ns = (float*)p;
    }

    float* hbuf; { void* p; cudaGetSymbolAddress(&p, d_h); hbuf = (float*)p; }
    int* rowptr_base; { void* p; cudaGetSymbolAddress(&p, d_rowptr); rowptr_base = (int*)p; }
    int4* edges_base; { void* p; cudaGetSymbolAddress(&p, d_edges);  edges_base  = (int4*)p; }
    __nv_bfloat16 *Ahi, *Alo, *W1Thi, *W1Tlo, *HMhi, *HMlo, *W2Thi, *W2Tlo;
    { void* p; cudaGetSymbolAddress(&p, d_Ahi);   Ahi   = (__nv_bfloat16*)p; }
    { void* p; cudaGetSymbolAddress(&p, d_Alo);   Alo   = (__nv_bfloat16*)p; }
    { void* p; cudaGetSymbolAddress(&p, d_W1Thi); W1Thi = (__nv_bfloat16*)p; }
    { void* p; cudaGetSymbolAddress(&p, d_W1Tlo); W1Tlo = (__nv_bfloat16*)p; }
    { void* p; cudaGetSymbolAddress(&p, d_HMhi);  HMhi  = (__nv_bfloat16*)p; }
    { void* p; cudaGetSymbolAddress(&p, d_HMlo);  HMlo  = (__nv_bfloat16*)p; }
    { void* p; cudaGetSymbolAddress(&p, d_W2Thi); W2Thi = (__nv_bfloat16*)p; }
    { void* p; cudaGetSymbolAddress(&p, d_W2Tlo); W2Tlo = (__nv_bfloat16*)p; }

    // (0-2) bf16 split conversions
    convA_kernel<<<(NN * DD / 4 + 255) / 256, 256>>>(features0, Ahi, Alo, NN * DD / 4);
    convWT_kernel<<<(DD * HH + 255) / 256, 256>>>(W1, W1Thi, W1Tlo, DD, HH);
    convWT_kernel<<<(HH * CC + 255) / 256, 256>>>(W2, W2Thi, W2Tlo, HH, CC);

    // (3) GEMM1: hm = relu(F@W1 + b1) -> bf16 hi/lo  [profiled launch index]
    {
        dim3 grid(MT, HH / 128);
        hmma_gemm_kernel<128, false><<<grid, 256>>>(
            Ahi, Alo, W1Thi, W1Tlo, NN, b1, HMhi, HMlo,
            nullptr, nullptr, nullptr, nullptr);
    }

    // CSR build
    zero_deg_kernel<<<(GG * NN + 255) / 256, 256>>>();
    hist_kernel<<<(GG * EE + 255) / 256, 256>>>(dst);
    { dim3 g1(NBLK, GG); scan1_kernel<<<g1, 1024>>>(); }
    scan2_kernel<<<1, 32>>>();
    scan3_kernel<<<(GG * NN + 255) / 256, 256>>>();
    scatter_kernel<<<(GG * EE + 255) / 256, 256>>>(src, dst, e_edges);

    // Label propagation: 3 graphs x 2 layers
    int pblocks = (NN * 32 + 255) / 256;
    for (int g = 0; g < GG; g++) {
        propagate_kernel<<<pblocks, 256>>>(
            label_init, edges_base + (size_t)g * EE,
            rowptr_base + g * (NN + 1),
            train_mask, labels_oh, attention, g, 0, 0, hbuf, lp);
        propagate_kernel<<<pblocks, 256>>>(
            hbuf, edges_base + (size_t)g * EE,
            rowptr_base + g * (NN + 1),
            train_mask, labels_oh, attention, g, 1, 1, hbuf, lp);
    }

    // GEMM2: ns = hm@W2 + b2, fused combine into out
    {
        dim3 grid(MT, 1);
        hmma_gemm_kernel<64, true><<<grid, 256>>>(
            HMhi, HMlo, W2Thi, W2Tlo, NN, b2, nullptr, nullptr,
            alpha, lp, ns, out);
    }
}

// round 5
// speedup vs baseline: 1.6080x; 1.1549x over previous
#include <cuda_runtime.h>
#include <cuda_bf16.h>
#include <cuda_fp16.h>
#include <math.h>
#include <cstdint>

// Problem constants (HGCF_3221225472207)
constexpr int NN = 50000;   // nodes
constexpr int CC = 64;      // classes
constexpr int GG = 3;       // metapath graphs
constexpr int EE = 1200000; // edges per graph
constexpr int DD = 256;     // input feat dim
constexpr int HH = 256;     // hidden dim
constexpr int NBLK = 49;    // ceil(NN/1024) scan blocks per graph
constexpr int MT = (NN + 127) / 128; // 391 M-tiles

// ---------------- device scratch (static, no allocation) ----------------
__device__ int   d_rowptr[GG * (NN + 1)];
__device__ int   d_cursor[GG * NN];
__device__ int   d_bsum[GG * 64];
__device__ int4  d_edges[(size_t)GG * EE];
__device__ __half d_l16[(size_t)NN * CC];          // label_init fp16
__device__ __half d_h16[(size_t)GG * NN * CC];     // per-graph layer0 out fp16
__device__ float  d_h2[(size_t)GG * NN * CC];      // per-graph layer1 out fp32
__device__ float d_lp_fb[(size_t)NN * CC];
__device__ float d_ns_fb[(size_t)NN * CC];
// bf16 split operands
__device__ __nv_bfloat16 d_Ahi[(size_t)NN * DD];
__device__ __nv_bfloat16 d_Alo[(size_t)NN * DD];
__device__ __nv_bfloat16 d_W1Thi[HH * DD];   // [n=256, k=256] = W1^T
__device__ __nv_bfloat16 d_W1Tlo[HH * DD];
__device__ __nv_bfloat16 d_HMhi[(size_t)NN * HH];
__device__ __nv_bfloat16 d_HMlo[(size_t)NN * HH];
__device__ __nv_bfloat16 d_W2Thi[CC * HH];   // [n=64, k=256] = W2^T
__device__ __nv_bfloat16 d_W2Tlo[CC * HH];

// ---------------- warp MMA / async-copy helpers ----------------
__device__ __forceinline__ uint32_t smem_u32(const void* p) {
    uint32_t a;
    asm("{ .reg .u64 t; cvta.to.shared.u64 t, %1; cvt.u32.u64 %0, t; }" : "=r"(a) : "l"(p));
    return a;
}
__device__ __forceinline__ void ldsm_x4(uint32_t (&r)[4], uint32_t addr) {
    asm volatile("ldmatrix.sync.aligned.m8n8.x4.shared.b16 {%0,%1,%2,%3}, [%4];"
                 : "=r"(r[0]), "=r"(r[1]), "=r"(r[2]), "=r"(r[3]) : "r"(addr));
}
__device__ __forceinline__ void mma_bf16(float* c, const uint32_t (&a)[4],
                                         uint32_t b0, uint32_t b1) {
    asm volatile(
        "mma.sync.aligned.m16n8k16.row.col.f32.bf16.bf16.f32 "
        "{%0,%1,%2,%3}, {%4,%5,%6,%7}, {%8,%9}, {%0,%1,%2,%3};"
        : "+f"(c[0]), "+f"(c[1]), "+f"(c[2]), "+f"(c[3])
        : "r"(a[0]), "r"(a[1]), "r"(a[2]), "r"(a[3]), "r"(b0), "r"(b1));
}
__device__ __forceinline__ void cp16(uint32_t dst, const void* src, bool pred) {
    int sz = pred ? 16 : 0;
    asm volatile("cp.async.cg.shared.global [%0], [%1], 16, %2;"
                 :: "r"(dst), "l"(src), "r"(sz));
}
#define CP_COMMIT asm volatile("cp.async.commit_group;" ::: "memory")
#define CP_WAIT1  asm volatile("cp.async.wait_group 1;" ::: "memory")
#define CP_WAIT0  asm volatile("cp.async.wait_group 0;" ::: "memory")

// ---------------- bf16 split conversion kernels ----------------
__global__ void convA_kernel(const float* __restrict__ x,
                             __nv_bfloat16* __restrict__ hi,
                             __nv_bfloat16* __restrict__ lo, int n4) {
    int i = blockIdx.x * blockDim.x + threadIdx.x;
    if (i >= n4) return;
    float4 v = ((const float4*)x)[i];
    __nv_bfloat16 h[4], l[4];
    float vv[4] = {v.x, v.y, v.z, v.w};
    #pragma unroll
    for (int j = 0; j < 4; j++) {
        h[j] = __float2bfloat16(vv[j]);
        l[j] = __float2bfloat16(vv[j] - __bfloat162float(h[j]));
    }
    ((uint2*)hi)[i] = *(uint2*)h;
    ((uint2*)lo)[i] = *(uint2*)l;
}

// transpose + split: out[n*K + k] = in[k*Nc + n]
__global__ void convWT_kernel(const float* __restrict__ in,
                              __nv_bfloat16* __restrict__ hi,
                              __nv_bfloat16* __restrict__ lo, int K, int Nc) {
    int i = blockIdx.x * blockDim.x + threadIdx.x;
    if (i >= K * Nc) return;
    int n = i / K, k = i - n * K;
    float v = in[(size_t)k * Nc + n];
    __nv_bfloat16 h = __float2bfloat16(v);
    hi[i] = h;
    lo[i] = __float2bfloat16(v - __bfloat162float(h));
}

// float -> fp16 (label_init)
__global__ void convL16_kernel(const float* __restrict__ x, int n2) {
    int i = blockIdx.x * blockDim.x + threadIdx.x;
    if (i >= n2) return;
    float2 v = ((const float2*)x)[i];
    ((__half2*)d_l16)[i] = __floats2half2_rn(v.x, v.y);
}

// ---------------- HMMA split GEMM with cp.async double buffering --------
// C[M, Ntile] = Ahi*Bhi + Alo*Bhi + Ahi*Blo, K=256, fp32 accum.
// BM=128, BK=32, 256 threads. BN=128: warps 2x4 (64x32 tile); BN=64: 4x2.
// COMBINE=false: relu(C+bias) -> bf16 hi/lo split.
// COMBINE=true : ns=C+bias; lp = sum_g att_g*h2_g; out = sig(a)*lp+(1-sig)*ns.
template <int BN, bool COMBINE>
__global__ void __launch_bounds__(256) hmma_gemm_kernel(
    const __nv_bfloat16* __restrict__ Ahi, const __nv_bfloat16* __restrict__ Alo,
    const __nv_bfloat16* __restrict__ Bhi, const __nv_bfloat16* __restrict__ Blo,
    int M, const float* __restrict__ bias,
    __nv_bfloat16* __restrict__ outHi, __nv_bfloat16* __restrict__ outLo,
    const float* __restrict__ attention,
    const float* __restrict__ h2_0, const float* __restrict__ h2_1,
    const float* __restrict__ h2_2,
    const float* __restrict__ alpha, float* __restrict__ lp,
    float* __restrict__ ns, float* __restrict__ outF) {
    constexpr int STRIDE = 40;                 // bf16 units per smem row
    constexpr int ASTAGE = 128 * STRIDE;       // one hi or lo A tile (units)
    constexpr int BSTAGE = BN * STRIDE;
    constexpr int BOFF = 4 * ASTAGE;           // B region offset (units)
    constexpr int WARPS_M = (BN == 128) ? 2 : 4;
    constexpr int WARPS_N = (BN == 128) ? 4 : 2;
    constexpr int WM = 128 / WARPS_M;
    constexpr int MF = WM / 16;
    constexpr int NP = 2;

    extern __shared__ __nv_bfloat16 smem[];
    uint32_t sbase = smem_u32(smem);

    int tid = threadIdx.x;
    int wid = tid >> 5, lane = tid & 31;
    int bm = blockIdx.x * 128;
    int bn = blockIdx.y * BN;
    int wm0 = (wid / WARPS_N) * WM;
    int wn0 = (wid % WARPS_N) * 32;

    float acc[MF][2 * NP][4];
    #pragma unroll
    for (int i = 0; i < MF; i++)
        #pragma unroll
        for (int j = 0; j < 2 * NP; j++)
            #pragma unroll
            for (int q = 0; q < 4; q++) acc[i][j][q] = 0.f;

    int a_row = tid >> 2, a_ch = tid & 3;

    auto issue_stage = [&](int kt, int st) {
        int k0 = kt * 32;
        #pragma unroll
        for (int j = 0; j < 2; j++) {
            int row = a_row + j * 64;
            int gm = bm + row;
            bool p = gm < M;
            uint32_t off = (uint32_t)(st * 2 * ASTAGE + row * STRIDE + a_ch * 8) * 2;
            cp16(sbase + off, Ahi + (size_t)gm * 256 + k0 + a_ch * 8, p);
            cp16(sbase + off + ASTAGE * 2, Alo + (size_t)gm * 256 + k0 + a_ch * 8, p);
        }
        #pragma unroll
        for (int j = 0; j < BN / 64; j++) {
            int row = a_row + j * 64;
            uint32_t off = (uint32_t)(BOFF + st * 2 * BSTAGE + row * STRIDE + a_ch * 8) * 2;
            cp16(sbase + off, Bhi + (size_t)(bn + row) * 256 + k0 + a_ch * 8, true);
            cp16(sbase + off + BSTAGE * 2, Blo + (size_t)(bn + row) * 256 + k0 + a_ch * 8, true);
        }
        CP_COMMIT;
    };

    int lrow = lane & 15, lch = lane >> 4;

    issue_stage(0, 0);
    for (int kt = 0; kt < 8; kt++) {
        int st = kt & 1;
        if (kt < 7) { issue_stage(kt + 1, st ^ 1); CP_WAIT1; }
        else        { CP_WAIT0; }
        __syncthreads();

        #pragma unroll
        for (int ks = 0; ks < 2; ks++) {
            uint32_t ah[MF][4], al[MF][4], bh[NP][4], bl[NP][4];
            #pragma unroll
            for (int mf = 0; mf < MF; mf++) {
                uint32_t off = sbase + (uint32_t)(st * 2 * ASTAGE +
                    (wm0 + mf * 16 + lrow) * STRIDE + (ks * 2 + lch) * 8) * 2;
                ldsm_x4(ah[mf], off);
                ldsm_x4(al[mf], off + ASTAGE * 2);
            }
            #pragma unroll
            for (int np = 0; np < NP; np++) {
                uint32_t off = sbase + (uint32_t)(BOFF + st * 2 * BSTAGE +
                    (wn0 + np * 16 + lrow) * STRIDE + (ks * 2 + lch) * 8) * 2;
                ldsm_x4(bh[np], off);
                ldsm_x4(bl[np], off + BSTAGE * 2);
            }
            #pragma unroll
            for (int mf = 0; mf < MF; mf++)
                #pragma unroll
                for (int np = 0; np < NP; np++) {
                    mma_bf16(acc[mf][2 * np + 0], ah[mf], bh[np][0], bh[np][2]);
                    mma_bf16(acc[mf][2 * np + 1], ah[mf], bh[np][1], bh[np][3]);
                    mma_bf16(acc[mf][2 * np + 0], al[mf], bh[np][0], bh[np][2]);
                    mma_bf16(acc[mf][2 * np + 1], al[mf], bh[np][1], bh[np][3]);
                    mma_bf16(acc[mf][2 * np + 0], ah[mf], bl[np][0], bl[np][2]);
                    mma_bf16(acc[mf][2 * np + 1], ah[mf], bl[np][1], bl[np][3]);
                }
        }
        __syncthreads();
    }

    // epilogue: c-frag thread t holds (m = t/4 [,+8], n = 2*(t%4)+{0,1})
    int mrow = lane >> 2, npair = lane & 3;
    #pragma unroll
    for (int mf = 0; mf < MF; mf++) {
        #pragma unroll
        for (int half = 0; half < 2; half++) {
            int gm = bm + wm0 + mf * 16 + mrow + half * 8;
            if (gm >= M) continue;
            float sg = 0.f, att0 = 0.f, att1 = 0.f, att2 = 0.f;
            if (COMBINE) {
                float a0 = attention[gm * 3 + 0];
                float a1 = attention[gm * 3 + 1];
                float a2 = attention[gm * 3 + 2];
                float mx = fmaxf(a0, fmaxf(a1, a2));
                float e0 = expf(a0 - mx), e1 = expf(a1 - mx), e2 = expf(a2 - mx);
                float den = e0 + e1 + e2;
                att0 = e0 / den; att1 = e1 / den; att2 = e2 / den;
                sg = 1.f / (1.f + expf(-alpha[gm]));
            }
            #pragma unroll
            for (int nf = 0; nf < 2 * NP; nf++) {
                int gn = bn + wn0 + nf * 8 + 2 * npair;
                float v0 = acc[mf][nf][half * 2 + 0] + bias[gn];
                float v1 = acc[mf][nf][half * 2 + 1] + bias[gn + 1];
                if (!COMBINE) {
                    v0 = fmaxf(v0, 0.f);
                    v1 = fmaxf(v1, 0.f);
                    __nv_bfloat16 h0 = __float2bfloat16(v0);
                    __nv_bfloat16 h1 = __float2bfloat16(v1);
                    __nv_bfloat16 l0 = __float2bfloat16(v0 - __bfloat162float(h0));
                    __nv_bfloat16 l1 = __float2bfloat16(v1 - __bfloat162float(h1));
                    size_t base = (size_t)gm * 256 + gn;
                    __nv_bfloat162 hp; hp.x = h0; hp.y = h1;
                    __nv_bfloat162 lo2; lo2.x = l0; lo2.y = l1;
                    *(__nv_bfloat162*)(outHi + base) = hp;
                    *(__nv_bfloat162*)(outLo + base) = lo2;
                } else {
                    size_t base = (size_t)gm * 64 + gn;
                    float2 o0 = *(const float2*)(h2_0 + base);
                    float2 o1 = *(const float2*)(h2_1 + base);
                    float2 o2 = *(const float2*)(h2_2 + base);
                    float lp0 = att0 * o0.x + att1 * o1.x + att2 * o2.x;
                    float lp1 = att0 * o0.y + att1 * o1.y + att2 * o2.y;
                    float2 lpv; lpv.x = lp0; lpv.y = lp1;
                    float2 nsv; nsv.x = v0; nsv.y = v1;
                    float2 ov;
                    ov.x = sg * lp0 + (1.f - sg) * v0;
                    ov.y = sg * lp1 + (1.f - sg) * v1;
                    *(float2*)(lp + base)   = lpv;
                    *(float2*)(ns + base)   = nsv;
                    *(float2*)(outF + base) = ov;
                }
            }
        }
    }
}

// ---------------- CSR build ----------------
__global__ void zero_deg_kernel() {
    int i = blockIdx.x * blockDim.x + threadIdx.x;
    if (i < GG * NN) d_cursor[i] = 0;
}

__global__ void hist_kernel(const int* __restrict__ dst) {
    int i = blockIdx.x * blockDim.x + threadIdx.x;
    if (i >= GG * EE) return;
    int g = i / EE;
    atomicAdd(&d_cursor[g * NN + dst[i]], 1);
}

__global__ void scan1_kernel() {
    int g = blockIdx.y;
    int tid = threadIdx.x;
    int i = blockIdx.x * 1024 + tid;
    int v = (i < NN) ? d_cursor[g * NN + i] : 0;
    unsigned lane = tid & 31, w = tid >> 5;
    int x = v;
    #pragma unroll
    for (int o = 1; o < 32; o <<= 1) {
        int t = __shfl_up_sync(0xffffffffu, x, o);
        if (lane >= o) x += t;
    }
    __shared__ int wsum[32];
    if (lane == 31) wsum[w] = x;
    __syncthreads();
    if (w == 0) {
        int y = wsum[lane];
        #pragma unroll
        for (int o = 1; o < 32; o <<= 1) {
            int t = __shfl_up_sync(0xffffffffu, y, o);
            if (lane >= o) y += t;
        }
        wsum[lane] = y;
    }
    __syncthreads();
    int incl = x + (w > 0 ? wsum[w - 1] : 0);
    int excl = incl - v;
    if (i < NN) d_rowptr[g * (NN + 1) + i] = excl;
    if (tid == 1023) d_bsum[g * 64 + blockIdx.x] = incl;
}

__global__ void scan2_kernel() {
    int g = threadIdx.x;
    if (g >= GG) return;
    int off = 0;
    for (int b = 0; b < NBLK; b++) {
        int t = d_bsum[g * 64 + b];
        d_bsum[g * 64 + b] = off;
        off += t;
    }
    d_rowptr[g * (NN + 1) + NN] = off;
}

__global__ void scan3_kernel() {
    int i = blockIdx.x * blockDim.x + threadIdx.x;
    if (i >= GG * NN) return;
    int g = i / NN, n = i - g * NN;
    int val = d_rowptr[g * (NN + 1) + n] + d_bsum[g * 64 + (n >> 10)];
    d_rowptr[g * (NN + 1) + n] = val;
    d_cursor[g * NN + n] = val;
}

__global__ void scatter_kernel(const int* __restrict__ src,
                               const int* __restrict__ dst,
                               const float* __restrict__ e_edges) {
    int i = blockIdx.x * blockDim.x + threadIdx.x;
    if (i >= GG * EE) return;
    int g = i / EE;
    int v = dst[i];
    int p = atomicAdd(&d_cursor[g * NN + v], 1);
    float e0 = expf(e_edges[i]);
    float e1 = expf(e_edges[(size_t)GG * EE + i]);
    d_edges[(size_t)g * EE + p] =
        make_int4(src[i], __float_as_int(e0), __float_as_int(e1), 0);
}

// ---------------- propagation: one warp per (graph, dst node) ----------
// layer 0: gather fp16 label_init, clamp, store fp16 h per graph
__global__ void prop_l0_kernel(const float* __restrict__ train_mask,
                               const float* __restrict__ labels_oh) {
    int w = (blockIdx.x * blockDim.x + threadIdx.x) >> 5;
    int lane = threadIdx.x & 31;
    if (w >= GG * NN) return;
    int g = w / NN, node = w - g * NN;
    const int4* edges = d_edges + (size_t)g * EE;
    const int* rp = d_rowptr + g * (NN + 1);
    int beg = rp[node], end = rp[node + 1];

    float s = 0.f;
    for (int j = beg + lane; j < end; j += 32) s += __int_as_float(edges[j].y);
    #pragma unroll
    for (int o = 16; o; o >>= 1) s += __shfl_xor_sync(0xffffffffu, s, o);
    float inv = (end > beg) ? 1.f / s : 0.f;

    const __half2* lbl = (const __half2*)d_l16;
    float2 acc = make_float2(0.f, 0.f);
    #pragma unroll 4
    for (int j = beg; j < end; j++) {
        int4 e = edges[j];
        float wt = __int_as_float(e.y) * inv;
        float2 v = __half22float2(lbl[(size_t)e.x * 32 + lane]);
        acc.x = fmaf(v.x, wt, acc.x);
        acc.y = fmaf(v.y, wt, acc.y);
    }
    float tm = train_mask[node];
    float ml = 1.f - tm;
    float2 oh = *(const float2*)(labels_oh + (size_t)node * CC + 2 * lane);
    float2 o;
    o.x = acc.x * ml + oh.x * tm;
    o.y = acc.y * ml + oh.y * tm;
    ((__half2*)d_h16)[(size_t)g * NN * 32 + (size_t)node * 32 + lane] =
        __floats2half2_rn(o.x, o.y);
}

// layer 1: gather fp16 h, clamp, store fp32 o per graph (attention in GEMM2)
__global__ void prop_l1_kernel(const float* __restrict__ train_mask,
                               const float* __restrict__ labels_oh) {
    int w = (blockIdx.x * blockDim.x + threadIdx.x) >> 5;
    int lane = threadIdx.x & 31;
    if (w >= GG * NN) return;
    int g = w / NN, node = w - g * NN;
    const int4* edges = d_edges + (size_t)g * EE;
    const int* rp = d_rowptr + g * (NN + 1);
    int beg = rp[node], end = rp[node + 1];

    float s = 0.f;
    for (int j = beg + lane; j < end; j += 32) s += __int_as_float(edges[j].z);
    #pragma unroll
    for (int o = 16; o; o >>= 1) s += __shfl_xor_sync(0xffffffffu, s, o);
    float inv = (end > beg) ? 1.f / s : 0.f;

    const __half2* hg = (const __half2*)d_h16 + (size_t)g * NN * 32;
    float2 acc = make_float2(0.f, 0.f);
    #pragma unroll 4
    for (int j = beg; j < end; j++) {
        int4 e = edges[j];
        float wt = __int_as_float(e.z) * inv;
        float2 v = __half22float2(hg[(size_t)e.x * 32 + lane]);
        acc.x = fmaf(v.x, wt, acc.x);
        acc.y = fmaf(v.y, wt, acc.y);
    }
    float tm = train_mask[node];
    float ml = 1.f - tm;
    float2 oh = *(const float2*)(labels_oh + (size_t)node * CC + 2 * lane);
    float2 o;
    o.x = acc.x * ml + oh.x * tm;
    o.y = acc.y * ml + oh.y * tm;
    *(float2*)(d_h2 + (size_t)g * NN * CC + (size_t)node * CC + 2 * lane) = o;
}

// ---------------- launch ----------------
extern "C" void kernel_launch(void* const* d_in, const int* in_sizes, int n_in,
                              void* d_out, int out_size) {
    const float* features0  = (const float*)d_in[0];
    const float* label_init = (const float*)d_in[1];
    const float* labels_oh  = (const float*)d_in[2];
    const float* train_mask = (const float*)d_in[3];
    const int*   src        = (const int*)d_in[4];
    const int*   dst        = (const int*)d_in[5];
    const float* e_edges    = (const float*)d_in[6];
    const float* attention  = (const float*)d_in[7];
    const float* alpha      = (const float*)d_in[8];
    const float* W1         = (const float*)d_in[9];
    const float* b1         = (const float*)d_in[10];
    const float* W2         = (const float*)d_in[11];
    const float* b2         = (const float*)d_in[12];

    float* out = (float*)d_out;
    float* lp;
    float* ns;
    if (out_size >= 3 * NN * CC) {
        lp = out + (size_t)NN * CC;
        ns = out + 2 * (size_t)NN * CC;
    } else {
        void* p;
        cudaGetSymbolAddress(&p, d_lp_fb); lp = (float*)p;
        cudaGetSymbolAddress(&p, d_ns_fb); ns = (float*)p;
    }

    float* h2base; { void* p; cudaGetSymbolAddress(&p, d_h2); h2base = (float*)p; }
    __nv_bfloat16 *Ahi, *Alo, *W1Thi, *W1Tlo, *HMhi, *HMlo, *W2Thi, *W2Tlo;
    { void* p; cudaGetSymbolAddress(&p, d_Ahi);   Ahi   = (__nv_bfloat16*)p; }
    { void* p; cudaGetSymbolAddress(&p, d_Alo);   Alo   = (__nv_bfloat16*)p; }
    { void* p; cudaGetSymbolAddress(&p, d_W1Thi); W1Thi = (__nv_bfloat16*)p; }
    { void* p; cudaGetSymbolAddress(&p, d_W1Tlo); W1Tlo = (__nv_bfloat16*)p; }
    { void* p; cudaGetSymbolAddress(&p, d_HMhi);  HMhi  = (__nv_bfloat16*)p; }
    { void* p; cudaGetSymbolAddress(&p, d_HMlo);  HMlo  = (__nv_bfloat16*)p; }
    { void* p; cudaGetSymbolAddress(&p, d_W2Thi); W2Thi = (__nv_bfloat16*)p; }
    { void* p; cudaGetSymbolAddress(&p, d_W2Tlo); W2Tlo = (__nv_bfloat16*)p; }

    constexpr int SMEM1 = (4 * 128 * 40 + 4 * 128 * 40) * 2; // 81920
    constexpr int SMEM2 = (4 * 128 * 40 + 4 * 64 * 40) * 2;  // 61440
    cudaFuncSetAttribute(hmma_gemm_kernel<128, false>,
                         cudaFuncAttributeMaxDynamicSharedMemorySize, SMEM1);
    cudaFuncSetAttribute(hmma_gemm_kernel<64, true>,
                         cudaFuncAttributeMaxDynamicSharedMemorySize, SMEM2);

    // (0-2) bf16 split conversions
    convA_kernel<<<(NN * DD / 4 + 255) / 256, 256>>>(features0, Ahi, Alo, NN * DD / 4);
    convWT_kernel<<<(DD * HH + 255) / 256, 256>>>(W1, W1Thi, W1Tlo, DD, HH);
    convWT_kernel<<<(HH * CC + 255) / 256, 256>>>(W2, W2Thi, W2Tlo, HH, CC);

    // (3) GEMM1: hm = relu(F@W1 + b1) -> bf16 hi/lo  [profiled launch index]
    {
        dim3 grid(MT, HH / 128);
        hmma_gemm_kernel<128, false><<<grid, 256, SMEM1>>>(
            Ahi, Alo, W1Thi, W1Tlo, NN, b1, HMhi, HMlo,
            nullptr, nullptr, nullptr, nullptr, nullptr, nullptr, nullptr, nullptr);
    }

    // label_init -> fp16
    convL16_kernel<<<(NN * CC / 2 + 255) / 256, 256>>>(label_init, NN * CC / 2);

    // CSR build
    zero_deg_kernel<<<(GG * NN + 255) / 256, 256>>>();
    hist_kernel<<<(GG * EE + 255) / 256, 256>>>(dst);
    { dim3 g1(NBLK, GG); scan1_kernel<<<g1, 1024>>>(); }
    scan2_kernel<<<1, 32>>>();
    scan3_kernel<<<(GG * NN + 255) / 256, 256>>>();
    scatter_kernel<<<(GG * EE + 255) / 256, 256>>>(src, dst, e_edges);

    // Label propagation: all graphs batched per layer
    int pblocks = (GG * NN * 32 + 255) / 256;
    prop_l0_kernel<<<pblocks, 256>>>(train_mask, labels_oh);
    prop_l1_kernel<<<pblocks, 256>>>(train_mask, labels_oh);

    // GEMM2: ns = hm@W2 + b2; fused lp (attention mix of h2_g) + combine
    {
        dim3 grid(MT, 1);
        hmma_gemm_kernel<64, true><<<grid, 256, SMEM2>>>(
            HMhi, HMlo, W2Thi, W2Tlo, NN, b2, nullptr, nullptr,
            attention, h2base, h2base + (size_t)NN * CC, h2base + 2 * (size_t)NN * CC,
            alpha, lp, ns, out);
    }
}